// round 10
// baseline (speedup 1.0000x reference)
#include <cuda_runtime.h>
#include <cuda_bf16.h>

#define BATCH 8
#define CH    256
#define NPOS  4096
#define IDIM  32

typedef unsigned long long u64;
typedef unsigned int u32;

__device__ __forceinline__ u64 pack2(float lo, float hi) {
    u64 r; asm("mov.b64 %0, {%1, %2};" : "=l"(r) : "f"(lo), "f"(hi)); return r;
}
__device__ __forceinline__ u64 ffma2(u64 a, u64 b, u64 c) {
    u64 d; asm("fma.rn.f32x2 %0, %1, %2, %3;" : "=l"(d) : "l"(a), "l"(b), "l"(c)); return d;
}
__device__ __forceinline__ u64 fmul2(u64 a, u64 b) {
    u64 d; asm("mul.rn.f32x2 %0, %1, %2;" : "=l"(d) : "l"(a), "l"(b)); return d;
}
__device__ __forceinline__ u64 fadd2(u64 a, u64 b) {
    u64 d; asm("add.rn.f32x2 %0, %1, %2;" : "=l"(d) : "l"(a), "l"(b)); return d;
}
__device__ __forceinline__ float2 unpack2(u64 a) {
    float2 f; asm("mov.b64 {%0, %1}, %2;" : "=f"(f.x), "=f"(f.y) : "l"(a)); return f;
}
__device__ __forceinline__ u32 bf2(float lo, float hi) {   // {lo16, hi16} packed bf16x2
    u32 r; asm("cvt.rn.bf16x2.f32 %0, %1, %2;" : "=r"(r) : "f"(hi), "f"(lo)); return r;
}
__device__ __forceinline__ u32 smem_u32(const void* p) {
    u32 a; asm("{ .reg .u64 t; cvta.to.shared.u64 t, %1; cvt.u32.u64 %0, t; }" : "=r"(a) : "l"(p));
    return a;
}
__device__ __forceinline__ void mma16816(float* d, u32 a0, u32 a1, u32 a2, u32 a3,
                                         u32 b0, u32 b1) {
    asm volatile("mma.sync.aligned.m16n8k16.row.col.f32.bf16.bf16.f32 "
                 "{%0,%1,%2,%3}, {%4,%5,%6,%7}, {%8,%9}, {%0,%1,%2,%3};"
                 : "+f"(d[0]), "+f"(d[1]), "+f"(d[2]), "+f"(d[3])
                 : "r"(a0), "r"(a1), "r"(a2), "r"(a3), "r"(b0), "r"(b1));
}
__device__ __forceinline__ void ldsm4(u32& r0, u32& r1, u32& r2, u32& r3, u32 a) {
    asm volatile("ldmatrix.sync.aligned.m8n8.x4.shared.b16 {%0,%1,%2,%3}, [%4];"
                 : "=r"(r0), "=r"(r1), "=r"(r2), "=r"(r3) : "r"(a));
}
__device__ __forceinline__ void cpa16(u32 dst, const void* src) {
    asm volatile("cp.async.cg.shared.global [%0], [%1], 16;" :: "r"(dst), "l"(src));
}
__device__ __forceinline__ void cpa_commit() { asm volatile("cp.async.commit_group;" ::: "memory"); }
__device__ __forceinline__ void cpa_wait0()  { asm volatile("cp.async.wait_group 0;" ::: "memory"); }
__device__ __forceinline__ void cpa_wait1()  { asm volatile("cp.async.wait_group 1;" ::: "memory"); }

// Fast exp on the FMA pipe (no MUFU)
__device__ __forceinline__ void exp_pair(float s0, float s1, float& p0, float& p1) {
    const float MAGIC = 12582912.f;   // 1.5 * 2^23
    u64 t2  = fmul2(pack2(s0, s1), pack2(1.4426950408889634f, 1.4426950408889634f));
    u64 r2  = fadd2(t2, pack2(MAGIC, MAGIC));
    u64 rm2 = fadd2(r2, pack2(-MAGIC, -MAGIC));
    u64 f2  = ffma2(rm2, pack2(-1.f, -1.f), t2);
    u64 q2  = ffma2(f2, pack2(1.3333558146e-3f, 1.3333558146e-3f),
                        pack2(9.6181291076e-3f, 9.6181291076e-3f));
    q2 = ffma2(f2, q2, pack2(5.5504108664e-2f, 5.5504108664e-2f));
    q2 = ffma2(f2, q2, pack2(2.4022650696e-1f, 2.4022650696e-1f));
    q2 = ffma2(f2, q2, pack2(6.9314718056e-1f, 6.9314718056e-1f));
    q2 = ffma2(f2, q2, pack2(1.f, 1.f));
    float2 rr = unpack2(r2);
    float2 qq = unpack2(q2);
    int e0 = (__float_as_int(rr.x) - 0x4B400000) << 23;
    int e1 = (__float_as_int(rr.y) - 0x4B400000) << 23;
    p0 = __int_as_float(__float_as_int(qq.x) + e0);
    p1 = __int_as_float(__float_as_int(qq.y) + e1);
}

// Scratch
__device__ __nv_bfloat16 g_xhi[BATCH * NPOS * CH];
__device__ __nv_bfloat16 g_xlo[BATCH * NPOS * CH];
__device__ __nv_bfloat16 g_whi[320 * CH];
__device__ __nv_bfloat16 g_wlo[320 * CH];
__device__ __nv_bfloat16 g_qhi[BATCH * NPOS * IDIM];
__device__ __nv_bfloat16 g_qlo[BATCH * NPOS * IDIM];
__device__ __nv_bfloat16 g_khi[BATCH * NPOS * IDIM];
__device__ __nv_bfloat16 g_klo[BATCH * NPOS * IDIM];
__device__ __nv_bfloat16 g_v  [BATCH * CH * NPOS];

// ---------------------------------------------------------------------------
// Kernel 0a: x -> split bf16, transposed to [b][n][c]
// ---------------------------------------------------------------------------
__global__ __launch_bounds__(256, 4)
void xprep_kernel(const float* __restrict__ x)
{
    const int b  = blockIdx.y;
    const int n0 = blockIdx.x * 64;
    const int tid = threadIdx.x;

    #pragma unroll
    for (int it = 0; it < 8; it++) {
        int i = tid + it * 256;
        int cp = i & 127, nq = i >> 7;
        int n = n0 + nq * 4;
        const float* p0 = x + ((size_t)b * CH + 2 * cp) * NPOS + n;
        float4 a = *(const float4*)p0;
        float4 c4 = *(const float4*)(p0 + NPOS);
        float av[4] = {a.x, a.y, a.z, a.w};
        float cv[4] = {c4.x, c4.y, c4.z, c4.w};
        #pragma unroll
        for (int e = 0; e < 4; e++) {
            float v0 = av[e], v1 = cv[e];
            u32 hw = bf2(v0, v1);
            float h0 = __int_as_float(hw << 16);
            float h1 = __int_as_float(hw & 0xFFFF0000u);
            u32 lw = bf2(v0 - h0, v1 - h1);
            size_t dst = ((size_t)b * NPOS + n + e) * CH + 2 * cp;
            *(u32*)((char*)g_xhi + dst * 2) = hw;
            *(u32*)((char*)g_xlo + dst * 2) = lw;
        }
    }
}

// ---------------------------------------------------------------------------
// Kernel 0b: W -> split bf16
// ---------------------------------------------------------------------------
__global__ __launch_bounds__(256, 4)
void wprep_kernel(const float* __restrict__ Wq, const float* __restrict__ Wk,
                  const float* __restrict__ Wv)
{
    const int gidx = blockIdx.x * 256 + threadIdx.x;
    #pragma unroll
    for (int i = 0; i < 8; i++) {
        int idx4 = gidx + i * 2560;
        int el = idx4 * 4;
        int r = el >> 8, c = el & 255;
        const float* src;
        if (r < 32)       src = Wq + r * CH + c;
        else if (r < 64)  src = Wk + (r - 32) * CH + c;
        else              src = Wv + (r - 64) * CH + c;
        float4 wv = *(const float4*)src;
        u32 h0 = bf2(wv.x, wv.y);
        u32 h1 = bf2(wv.z, wv.w);
        float f0 = __int_as_float(h0 << 16),        f1 = __int_as_float(h0 & 0xFFFF0000u);
        float f2 = __int_as_float(h1 << 16),        f3 = __int_as_float(h1 & 0xFFFF0000u);
        u32 l0 = bf2(wv.x - f0, wv.y - f1);
        u32 l1 = bf2(wv.z - f2, wv.w - f3);
        *(uint2*)((char*)g_whi + (size_t)el * 2) = make_uint2(h0, h1);
        *(uint2*)((char*)g_wlo + (size_t)el * 2) = make_uint2(l0, l1);
    }
}

// ---------------------------------------------------------------------------
// Kernel 1: QKV GEMM on HMMA (X b-frags via ldmatrix)
// ---------------------------------------------------------------------------
#define GX_PITCH 528
#define GSM_TOT  67584

__global__ __launch_bounds__(320, 2)
void qkv_gemm(const float* __restrict__ bq, const float* __restrict__ bk,
              const float* __restrict__ bv)
{
    extern __shared__ char sm[];
    const u32 smb = smem_u32(sm);

    const int b    = blockIdx.y;
    const int m0   = blockIdx.x * 64;
    const int tid  = threadIdx.x;
    const int w    = tid >> 5;
    const int lane = tid & 31;
    const int lr4  = lane >> 2;
    const int lc2  = (lane & 3) * 2;
    const int rbase = w * 32;
    const bool is_qk = (w < 2);

    {
        const __nv_bfloat16* xh = g_xhi + ((size_t)b * NPOS + m0) * CH;
        const __nv_bfloat16* xl = g_xlo + ((size_t)b * NPOS + m0) * CH;
        for (int i = tid; i < 4096; i += 320) {
            int plane = i >> 11;
            int row = (i >> 5) & 63;
            int seg = i & 31;
            const __nv_bfloat16* src = (plane ? xl : xh) + (size_t)row * CH + seg * 8;
            cpa16(smb + plane * 33792 + row * GX_PITCH + seg * 16, src);
        }
        cpa_commit();
        cpa_wait0();
    }
    __syncthreads();

    float d[2][8][4];
    #pragma unroll
    for (int mi = 0; mi < 2; mi++)
        #pragma unroll
        for (int nb = 0; nb < 8; nb++)
            #pragma unroll
            for (int r = 0; r < 4; r++) d[mi][nb][r] = 0.f;

    // canonical ldmatrix lane offset for B pairs (pitch 528)
    const u32 pbq_lane = ((lane & 7) + ((lane >> 4) & 1) * 8) * GX_PITCH
                       + ((lane >> 3) & 1) * 16;

    const char* whb = (const char*)g_whi;
    const char* wlb = (const char*)g_wlo;
    #pragma unroll 4
    for (int ks = 0; ks < 16; ks++) {
        const int kbyA = ks * 32 + (lane & 3) * 4;
        u32 aH[2][4], aL[2][4];
        #pragma unroll
        for (int mi = 0; mi < 2; mi++) {
            const char* pa = whb + (size_t)(rbase + mi * 16 + lr4) * 512 + kbyA;
            aH[mi][0] = *(const u32*)pa;
            aH[mi][1] = *(const u32*)(pa + 4096);
            aH[mi][2] = *(const u32*)(pa + 16);
            aH[mi][3] = *(const u32*)(pa + 4096 + 16);
        }
        if (is_qk) {
            #pragma unroll
            for (int mi = 0; mi < 2; mi++) {
                const char* pa = wlb + (size_t)(rbase + mi * 16 + lr4) * 512 + kbyA;
                aL[mi][0] = *(const u32*)pa;
                aL[mi][1] = *(const u32*)(pa + 4096);
                aL[mi][2] = *(const u32*)(pa + 16);
                aL[mi][3] = *(const u32*)(pa + 4096 + 16);
            }
        }
        #pragma unroll
        for (int p = 0; p < 4; p++) {
            u32 h0, h1, h2, h3;
            ldsm4(h0, h1, h2, h3, smb + pbq_lane + p * (16 * GX_PITCH) + ks * 32);
            mma16816(d[0][2*p],   aH[0][0], aH[0][1], aH[0][2], aH[0][3], h0, h1);
            mma16816(d[1][2*p],   aH[1][0], aH[1][1], aH[1][2], aH[1][3], h0, h1);
            mma16816(d[0][2*p+1], aH[0][0], aH[0][1], aH[0][2], aH[0][3], h2, h3);
            mma16816(d[1][2*p+1], aH[1][0], aH[1][1], aH[1][2], aH[1][3], h2, h3);
            if (is_qk) {
                u32 l0, l1, l2, l3;
                ldsm4(l0, l1, l2, l3, smb + 33792 + pbq_lane + p * (16 * GX_PITCH) + ks * 32);
                mma16816(d[0][2*p],   aH[0][0], aH[0][1], aH[0][2], aH[0][3], l0, l1);
                mma16816(d[1][2*p],   aH[1][0], aH[1][1], aH[1][2], aH[1][3], l0, l1);
                mma16816(d[0][2*p+1], aH[0][0], aH[0][1], aH[0][2], aH[0][3], l2, l3);
                mma16816(d[1][2*p+1], aH[1][0], aH[1][1], aH[1][2], aH[1][3], l2, l3);
                mma16816(d[0][2*p],   aL[0][0], aL[0][1], aL[0][2], aL[0][3], h0, h1);
                mma16816(d[1][2*p],   aL[1][0], aL[1][1], aL[1][2], aL[1][3], h0, h1);
                mma16816(d[0][2*p+1], aL[0][0], aL[0][1], aL[0][2], aL[0][3], h2, h3);
                mma16816(d[1][2*p+1], aL[1][0], aL[1][1], aL[1][2], aL[1][3], h2, h3);
            }
        }
    }

    if (!is_qk) {
        #pragma unroll
        for (int mi = 0; mi < 2; mi++) {
            int c0 = rbase - 64 + mi * 16 + lr4;
            int c1 = c0 + 8;
            float bv0 = bv[c0], bv1 = bv[c1];
            #pragma unroll
            for (int nb = 0; nb < 8; nb++) {
                int n = m0 + nb * 8 + lc2;
                u32 w0 = bf2(d[mi][nb][0] + bv0, d[mi][nb][1] + bv0);
                u32 w1 = bf2(d[mi][nb][2] + bv1, d[mi][nb][3] + bv1);
                *(u32*)((char*)g_v + ((size_t)(b * CH + c0) * NPOS + n) * 2) = w0;
                *(u32*)((char*)g_v + ((size_t)(b * CH + c1) * NPOS + n) * 2) = w1;
            }
        }
    }

    __syncthreads();
    float* bounce = (float*)sm;
    if (is_qk) {
        #pragma unroll
        for (int mi = 0; mi < 2; mi++) {
            int r = rbase + mi * 16 + lr4;
            #pragma unroll
            for (int nb = 0; nb < 8; nb++) {
                int n = nb * 8 + lc2;
                bounce[n * 68 + r]           = d[mi][nb][0];
                bounce[(n + 1) * 68 + r]     = d[mi][nb][1];
                bounce[n * 68 + r + 8]       = d[mi][nb][2];
                bounce[(n + 1) * 68 + r + 8] = d[mi][nb][3];
            }
        }
    }
    __syncthreads();

    for (int i = tid; i < 2048; i += 320) {
        int n = i >> 5, rp = i & 31;
        float2 f = *(const float2*)(bounce + n * 68 + rp * 2);
        bool isq = (rp < 16);
        int lr = isq ? 2 * rp : 2 * rp - 32;
        float b0 = isq ? bq[lr]     : bk[lr];
        float b1 = isq ? bq[lr + 1] : bk[lr + 1];
        float v0 = f.x + b0, v1 = f.y + b1;
        u32 hw = bf2(v0, v1);
        float h0 = __int_as_float(hw << 16);
        float h1 = __int_as_float(hw & 0xFFFF0000u);
        u32 lw = bf2(v0 - h0, v1 - h1);
        size_t base = (((size_t)b * NPOS + m0 + n) * IDIM + lr) * 2;
        if (isq) {
            *(u32*)((char*)g_qhi + base) = hw;
            *(u32*)((char*)g_qlo + base) = lw;
        } else {
            *(u32*)((char*)g_khi + base) = hw;
            *(u32*)((char*)g_klo + base) = lw;
        }
    }
}

// ---------------------------------------------------------------------------
// Kernel 2: attention, fused pipeline + ldmatrix fragments.
// 512 threads, M-tile 128, chunk 64 keys. P/V/K double-buffered, Q persistent.
// ---------------------------------------------------------------------------
#define LARR_OFF 0
#define AQ_OFF   1024
#define AK_OFF   (AQ_OFF + 20480)
#define AP_OFF   (AK_OFF + 20480)
#define AV_OFF   (AP_OFF + 36864)
#define ASM_TOT  (AV_OFF + 73728)        // 152576 B

// PV fused step: O[32m x 64c] += P[.,16k] * V[.,16k]^T  (all frags via ldmatrix)
__device__ __forceinline__ void pv_step(u32 Pa, u32 Va, int t,
        u32 pa_lane, u32 pb_lane, float (*o)[8][4])
{
    const u32 tof = (u32)(t * 32);
    u32 a[2][4];
    ldsm4(a[0][0], a[0][1], a[0][2], a[0][3], Pa + pa_lane + tof);
    ldsm4(a[1][0], a[1][1], a[1][2], a[1][3], Pa + pa_lane + 2304 + tof);
    #pragma unroll
    for (int p = 0; p < 4; p++) {
        u32 b0, b1, b2, b3;
        ldsm4(b0, b1, b2, b3, Va + pb_lane + p * 2304 + tof);
        mma16816(o[0][2*p],   a[0][0], a[0][1], a[0][2], a[0][3], b0, b1);
        mma16816(o[1][2*p],   a[1][0], a[1][1], a[1][2], a[1][3], b0, b1);
        mma16816(o[0][2*p+1], a[0][0], a[0][1], a[0][2], a[0][3], b2, b3);
        mma16816(o[1][2*p+1], a[1][0], a[1][1], a[1][2], a[1][3], b2, b3);
    }
}

// S fused step: S[16q x 8n] -> exp -> P   (K hi+lo frags in one ldmatrix.x4)
__device__ __forceinline__ void s_step(u32 Kb, char* Pd, int t,
        int h, int mA, int lc2, u32 ps_lane,
        const u32 (*ah)[4], const u32 (*al)[4], u64& lrA2, u64& lrB2)
{
    const int nbase = 32 * h + t * 8;
    u32 bh0, bh1, bl0, bl1, ch0, ch1, cl0, cl1;
    ldsm4(bh0, bh1, bl0, bl1, Kb + ps_lane + nbase * 80);
    ldsm4(ch0, ch1, cl0, cl1, Kb + ps_lane + nbase * 80 + 32);
    float d[4] = {0.f, 0.f, 0.f, 0.f};
    mma16816(d, ah[0][0], ah[0][1], ah[0][2], ah[0][3], bh0, bh1);
    mma16816(d, ah[0][0], ah[0][1], ah[0][2], ah[0][3], bl0, bl1);
    mma16816(d, al[0][0], al[0][1], al[0][2], al[0][3], bh0, bh1);
    mma16816(d, ah[1][0], ah[1][1], ah[1][2], ah[1][3], ch0, ch1);
    mma16816(d, ah[1][0], ah[1][1], ah[1][2], ah[1][3], cl0, cl1);
    mma16816(d, al[1][0], al[1][1], al[1][2], al[1][3], ch0, ch1);

    float pA0, pA1, pB0, pB1;
    exp_pair(d[0], d[1], pA0, pA1);
    exp_pair(d[2], d[3], pB0, pB1);
    lrA2 = fadd2(lrA2, pack2(pA0, pA1));
    lrB2 = fadd2(lrB2, pack2(pB0, pB1));
    const int c0 = nbase + lc2;
    *(u32*)(Pd + mA * 144 + c0 * 2)       = bf2(pA0, pA1);
    *(u32*)(Pd + (mA + 8) * 144 + c0 * 2) = bf2(pB0, pB1);
}

__global__ __launch_bounds__(512, 1)
void attn_kernel(const float* __restrict__ x,
                 const float* __restrict__ gamma,
                 float* __restrict__ out)
{
    extern __shared__ char sm[];
    float* larr = (float*)(sm + LARR_OFF);
    const u32 smb = smem_u32(sm);

    const int b    = blockIdx.y;
    const int m0   = blockIdx.x * 128;
    const int tid  = threadIdx.x;
    const int w    = tid >> 5;
    const int lane = tid & 31;
    const int g    = w >> 1;
    const int h    = w & 1;
    const int lr4  = lane >> 2;
    const int lc2  = (lane & 3) * 2;
    const int mb2  = (w & 3) * 32;
    const int cb0  = (w >> 2) * 64;

    // canonical ldmatrix lane offsets
    const u32 pa_lane = (u32)((mb2 + (lane & 7) + ((lane >> 3) & 1) * 8) * 144
                              + ((lane >> 4) & 1) * 16);
    const u32 pb_lane = (u32)((cb0 + (lane & 7) + ((lane >> 4) & 1) * 8) * 144
                              + ((lane >> 3) & 1) * 16);
    const u32 ps_lane = (u32)((lane & 7) * 80 + ((lane >> 3) & 1) * 16
                              + ((lane >> 4) & 1) * 5120);

    const __nv_bfloat16* qhb = g_qhi + ((size_t)b * NPOS + m0) * IDIM;
    const __nv_bfloat16* qlb = g_qlo + ((size_t)b * NPOS + m0) * IDIM;
    const __nv_bfloat16* khb = g_khi + (size_t)b * NPOS * IDIM;
    const __nv_bfloat16* klb = g_klo + (size_t)b * NPOS * IDIM;
    const __nv_bfloat16* vb  = g_v   + (size_t)b * CH * NPOS;

    auto stage_K = [&](int buf, int n0) {
        int j = tid & 3, row = (tid >> 2) & 63, plane = tid >> 8;
        cpa16(smb + AK_OFF + buf * 10240 + plane * 5120 + row * 80 + j * 16,
              (plane ? klb : khb) + (size_t)(n0 + row) * IDIM + j * 8);
    };
    auto stage_V = [&](int buf, int n0) {
        #pragma unroll
        for (int it = 0; it < 4; it++) {
            int idx = tid + it * 512;
            int c = idx >> 3, j = idx & 7;
            cpa16(smb + AV_OFF + buf * 36864 + c * 144 + j * 16,
                  vb + (size_t)c * NPOS + n0 + j * 8);
        }
    };

    // ---- Prologue ----
    #pragma unroll
    for (int it = 0; it < 2; it++) {
        int idx = tid + it * 512;
        int j = idx & 3, row = (idx >> 2) & 127, plane = idx >> 9;
        cpa16(smb + AQ_OFF + plane * 10240 + row * 80 + j * 16,
              (plane ? qlb : qhb) + (size_t)row * IDIM + j * 8);
    }
    stage_K(0, 0);
    cpa_commit();
    stage_V(0, 0);
    stage_K(1, 64);
    cpa_commit();
    cpa_wait1();
    __syncthreads();

    // Q a-frags via ldmatrix (persistent registers)
    u32 ah[2][4], al[2][4];
    {
        const u32 qa_lane = (u32)((g * 16 + (lane & 7) + ((lane >> 3) & 1) * 8) * 80
                                  + ((lane >> 4) & 1) * 16);
        ldsm4(ah[0][0], ah[0][1], ah[0][2], ah[0][3], smb + AQ_OFF + qa_lane);
        ldsm4(ah[1][0], ah[1][1], ah[1][2], ah[1][3], smb + AQ_OFF + qa_lane + 32);
        ldsm4(al[0][0], al[0][1], al[0][2], al[0][3], smb + AQ_OFF + 10240 + qa_lane);
        ldsm4(al[1][0], al[1][1], al[1][2], al[1][3], smb + AQ_OFF + 10240 + qa_lane + 32);
    }

    float o[2][8][4];
    #pragma unroll
    for (int mi = 0; mi < 2; mi++)
        #pragma unroll
        for (int cj = 0; cj < 8; cj++)
            #pragma unroll
            for (int r = 0; r < 4; r++) o[mi][cj][r] = 0.f;
    u64 lrA2 = 0ull, lrB2 = 0ull;
    const int mA = g * 16 + lr4;

    // S(0) peeled
    #pragma unroll
    for (int t = 0; t < 4; t++)
        s_step(smb + AK_OFF, sm + AP_OFF, t, h, mA, lc2, ps_lane, ah, al, lrA2, lrB2);
    cpa_wait0();
    __syncthreads();

    // ---- Main loop: iter kk does PV(kk) + S(kk+1) ----
    #pragma unroll 1
    for (int kk = 0; kk < 63; kk++) {
        stage_V((kk + 1) & 1, (kk + 1) * 64);
        if (kk < 62) stage_K(kk & 1, (kk + 2) * 64);
        cpa_commit();

        const u32 Pa = smb + AP_OFF + (kk & 1) * 18432;
        const u32 Va = smb + AV_OFF + (kk & 1) * 36864;
        const u32 Kb = smb + AK_OFF + ((kk + 1) & 1) * 10240;
        char*     Pd = sm  + AP_OFF + ((kk + 1) & 1) * 18432;

        #pragma unroll
        for (int t = 0; t < 4; t++) {
            pv_step(Pa, Va, t, pa_lane, pb_lane, o);
            s_step(Kb, Pd, t, h, mA, lc2, ps_lane, ah, al, lrA2, lrB2);
        }
        cpa_wait0();
        __syncthreads();
    }

    // Final PV(63)
    #pragma unroll
    for (int t = 0; t < 4; t++)
        pv_step(smb + AP_OFF + 18432, smb + AV_OFF + 36864, t, pa_lane, pb_lane, o);

    // ---- l reduction ----
    {
        float2 fa = unpack2(lrA2);
        float2 fb = unpack2(lrB2);
        float lA = fa.x + fa.y;
        float lB = fb.x + fb.y;
        #pragma unroll
        for (int off = 1; off <= 2; off <<= 1) {
            lA += __shfl_xor_sync(0xffffffffu, lA, off);
            lB += __shfl_xor_sync(0xffffffffu, lB, off);
        }
        if ((lane & 3) == 0) {
            larr[h * 128 + g * 16 + lr4]     = lA;
            larr[h * 128 + g * 16 + lr4 + 8] = lB;
        }
    }
    __syncthreads();

    // ---- Epilogue ----
    const float gm = gamma[0];
    const size_t gbase = (size_t)b * CH * NPOS + m0;
    #pragma unroll
    for (int mi = 0; mi < 2; mi++) {
        const int mAe = mb2 + mi * 16 + lr4;
        const int mBe = mAe + 8;
        const float recA = gm / (larr[mAe] + larr[128 + mAe]);
        const float recB = gm / (larr[mBe] + larr[128 + mBe]);
        #pragma unroll
        for (int cj = 0; cj < 8; cj++) {
            const int c0 = cb0 + cj * 8 + lc2;
            size_t gi0 = gbase + (size_t)c0 * NPOS;
            out[gi0 + mAe]        = o[mi][cj][0] * recA + x[gi0 + mAe];
            out[gi0 + NPOS + mAe] = o[mi][cj][1] * recA + x[gi0 + NPOS + mAe];
            out[gi0 + mBe]        = o[mi][cj][2] * recB + x[gi0 + mBe];
            out[gi0 + NPOS + mBe] = o[mi][cj][3] * recB + x[gi0 + NPOS + mBe];
        }
    }
}

// ---------------------------------------------------------------------------
extern "C" void kernel_launch(void* const* d_in, const int* in_sizes, int n_in,
                              void* d_out, int out_size)
{
    const float* x     = (const float*)d_in[0];
    const float* Wq    = (const float*)d_in[1];
    const float* bq    = (const float*)d_in[2];
    const float* Wk    = (const float*)d_in[3];
    const float* bk    = (const float*)d_in[4];
    const float* Wv    = (const float*)d_in[5];
    const float* bv    = (const float*)d_in[6];
    const float* gamma = (const float*)d_in[7];
    float* out = (float*)d_out;

    cudaFuncSetAttribute(qkv_gemm,    cudaFuncAttributeMaxDynamicSharedMemorySize, GSM_TOT);
    cudaFuncSetAttribute(attn_kernel, cudaFuncAttributeMaxDynamicSharedMemorySize, ASM_TOT);

    xprep_kernel<<<dim3(64, 8), 256>>>(x);
    wprep_kernel<<<10, 256>>>(Wq, Wk, Wv);
    qkv_gemm<<<dim3(64, 8), 320, GSM_TOT>>>(bq, bk, bv);
    attn_kernel<<<dim3(32, 8), 512, ASM_TOT>>>(x, gamma, out);
}

// round 11
// speedup vs baseline: 1.7877x; 1.7877x over previous
#include <cuda_runtime.h>
#include <cuda_bf16.h>
#include <cuda_fp16.h>

#define BATCH 8
#define CH    256
#define NPOS  4096
#define IDIM  32

typedef unsigned long long u64;
typedef unsigned int u32;

__device__ __forceinline__ u64 pack2(float lo, float hi) {
    u64 r; asm("mov.b64 %0, {%1, %2};" : "=l"(r) : "f"(lo), "f"(hi)); return r;
}
__device__ __forceinline__ u64 ffma2(u64 a, u64 b, u64 c) {
    u64 d; asm("fma.rn.f32x2 %0, %1, %2, %3;" : "=l"(d) : "l"(a), "l"(b), "l"(c)); return d;
}
__device__ __forceinline__ u64 fmul2(u64 a, u64 b) {
    u64 d; asm("mul.rn.f32x2 %0, %1, %2;" : "=l"(d) : "l"(a), "l"(b)); return d;
}
__device__ __forceinline__ u64 fadd2(u64 a, u64 b) {
    u64 d; asm("add.rn.f32x2 %0, %1, %2;" : "=l"(d) : "l"(a), "l"(b)); return d;
}
__device__ __forceinline__ float2 unpack2(u64 a) {
    float2 f; asm("mov.b64 {%0, %1}, %2;" : "=f"(f.x), "=f"(f.y) : "l"(a)); return f;
}
__device__ __forceinline__ u32 bf2(float lo, float hi) {   // {lo16, hi16} packed bf16x2
    u32 r; asm("cvt.rn.bf16x2.f32 %0, %1, %2;" : "=r"(r) : "f"(hi), "f"(lo)); return r;
}
__device__ __forceinline__ u32 hf2(float lo, float hi) {   // {lo16, hi16} packed f16x2
    u32 r; asm("cvt.rn.f16x2.f32 %0, %1, %2;" : "=r"(r) : "f"(hi), "f"(lo)); return r;
}
__device__ __forceinline__ u32 smem_u32(const void* p) {
    u32 a; asm("{ .reg .u64 t; cvta.to.shared.u64 t, %1; cvt.u32.u64 %0, t; }" : "=r"(a) : "l"(p));
    return a;
}
// bf16 MMA (PV path)
__device__ __forceinline__ void mma16816(float* d, u32 a0, u32 a1, u32 a2, u32 a3,
                                         u32 b0, u32 b1) {
    asm volatile("mma.sync.aligned.m16n8k16.row.col.f32.bf16.bf16.f32 "
                 "{%0,%1,%2,%3}, {%4,%5,%6,%7}, {%8,%9}, {%0,%1,%2,%3};"
                 : "+f"(d[0]), "+f"(d[1]), "+f"(d[2]), "+f"(d[3])
                 : "r"(a0), "r"(a1), "r"(a2), "r"(a3), "r"(b0), "r"(b1));
}
// fp16 MMA (S path + qkv GEMM)
__device__ __forceinline__ void mma16816h(float* d, u32 a0, u32 a1, u32 a2, u32 a3,
                                          u32 b0, u32 b1) {
    asm volatile("mma.sync.aligned.m16n8k16.row.col.f32.f16.f16.f32 "
                 "{%0,%1,%2,%3}, {%4,%5,%6,%7}, {%8,%9}, {%0,%1,%2,%3};"
                 : "+f"(d[0]), "+f"(d[1]), "+f"(d[2]), "+f"(d[3])
                 : "r"(a0), "r"(a1), "r"(a2), "r"(a3), "r"(b0), "r"(b1));
}
__device__ __forceinline__ void cpa16(u32 dst, const void* src) {
    asm volatile("cp.async.cg.shared.global [%0], [%1], 16;" :: "r"(dst), "l"(src));
}
__device__ __forceinline__ void cpa_commit() { asm volatile("cp.async.commit_group;" ::: "memory"); }
__device__ __forceinline__ void cpa_wait0()  { asm volatile("cp.async.wait_group 0;" ::: "memory"); }
__device__ __forceinline__ void cpa_wait1()  { asm volatile("cp.async.wait_group 1;" ::: "memory"); }

// Fast exp on the FMA pipe (no MUFU)
__device__ __forceinline__ void exp_pair(float s0, float s1, float& p0, float& p1) {
    const float MAGIC = 12582912.f;   // 1.5 * 2^23
    u64 t2  = fmul2(pack2(s0, s1), pack2(1.4426950408889634f, 1.4426950408889634f));
    u64 r2  = fadd2(t2, pack2(MAGIC, MAGIC));
    u64 rm2 = fadd2(r2, pack2(-MAGIC, -MAGIC));
    u64 f2  = ffma2(rm2, pack2(-1.f, -1.f), t2);
    u64 q2  = ffma2(f2, pack2(1.3333558146e-3f, 1.3333558146e-3f),
                        pack2(9.6181291076e-3f, 9.6181291076e-3f));
    q2 = ffma2(f2, q2, pack2(5.5504108664e-2f, 5.5504108664e-2f));
    q2 = ffma2(f2, q2, pack2(2.4022650696e-1f, 2.4022650696e-1f));
    q2 = ffma2(f2, q2, pack2(6.9314718056e-1f, 6.9314718056e-1f));
    q2 = ffma2(f2, q2, pack2(1.f, 1.f));
    float2 rr = unpack2(r2);
    float2 qq = unpack2(q2);
    int e0 = (__float_as_int(rr.x) - 0x4B400000) << 23;
    int e1 = (__float_as_int(rr.y) - 0x4B400000) << 23;
    p0 = __int_as_float(__float_as_int(qq.x) + e0);
    p1 = __int_as_float(__float_as_int(qq.y) + e1);
}

// Scratch
__device__ __half g_xh[BATCH * NPOS * CH];            // x fp16, transposed [b][n][c]
__device__ __half g_wh[320 * CH];                     // W fp16 [320 r][256 c]
__device__ __half g_qh[BATCH * NPOS * IDIM];          // q fp16 [b][m][32 i]
__device__ __half g_kh[BATCH * NPOS * IDIM];          // k fp16 [b][n][32 i]
__device__ __nv_bfloat16 g_v[BATCH * CH * NPOS];      // v bf16 [b][c][n]

// ---------------------------------------------------------------------------
// Kernel 0a: x -> fp16, transposed to [b][n][c]
// ---------------------------------------------------------------------------
__global__ __launch_bounds__(256, 4)
void xprep_kernel(const float* __restrict__ x)
{
    const int b  = blockIdx.y;
    const int n0 = blockIdx.x * 64;
    const int tid = threadIdx.x;

    #pragma unroll
    for (int it = 0; it < 8; it++) {
        int i = tid + it * 256;
        int cp = i & 127, nq = i >> 7;
        int n = n0 + nq * 4;
        const float* p0 = x + ((size_t)b * CH + 2 * cp) * NPOS + n;
        float4 a = *(const float4*)p0;
        float4 c4 = *(const float4*)(p0 + NPOS);
        float av[4] = {a.x, a.y, a.z, a.w};
        float cv[4] = {c4.x, c4.y, c4.z, c4.w};
        #pragma unroll
        for (int e = 0; e < 4; e++) {
            size_t dst = ((size_t)b * NPOS + n + e) * CH + 2 * cp;
            *(u32*)((char*)g_xh + dst * 2) = hf2(av[e], cv[e]);
        }
    }
}

// ---------------------------------------------------------------------------
// Kernel 0b: W (320 x 256) -> fp16
// ---------------------------------------------------------------------------
__global__ __launch_bounds__(256, 4)
void wprep_kernel(const float* __restrict__ Wq, const float* __restrict__ Wk,
                  const float* __restrict__ Wv)
{
    const int gidx = blockIdx.x * 256 + threadIdx.x;
    #pragma unroll
    for (int i = 0; i < 8; i++) {
        int idx4 = gidx + i * 2560;
        int el = idx4 * 4;
        int r = el >> 8, c = el & 255;
        const float* src;
        if (r < 32)       src = Wq + r * CH + c;
        else if (r < 64)  src = Wk + (r - 32) * CH + c;
        else              src = Wv + (r - 64) * CH + c;
        float4 wv = *(const float4*)src;
        *(uint2*)((char*)g_wh + (size_t)el * 2) =
            make_uint2(hf2(wv.x, wv.y), hf2(wv.z, wv.w));
    }
}

// ---------------------------------------------------------------------------
// Kernel 1: QKV GEMM, single-plane fp16 HMMA. grid (64,8), 320 threads.
// Warp w: rows w*32..+31 (w<2: q/k; w>=2: v). N-tile 64 positions.
// ---------------------------------------------------------------------------
#define GX_PITCH 528
#define GSM_TOT  33792

__global__ __launch_bounds__(320, 2)
void qkv_gemm(const float* __restrict__ bq, const float* __restrict__ bk,
              const float* __restrict__ bv)
{
    extern __shared__ char sm[];
    const u32 smb = smem_u32(sm);

    const int b    = blockIdx.y;
    const int m0   = blockIdx.x * 64;
    const int tid  = threadIdx.x;
    const int w    = tid >> 5;
    const int lane = tid & 31;
    const int lr4  = lane >> 2;
    const int lc2  = (lane & 3) * 2;
    const int rbase = w * 32;
    const bool is_qk = (w < 2);

    // Stage X tile [64 n][256 c] fp16
    {
        const __half* xh = g_xh + ((size_t)b * NPOS + m0) * CH;
        for (int i = tid; i < 2048; i += 320) {
            int row = i >> 5, seg = i & 31;
            cpa16(smb + row * GX_PITCH + seg * 16, xh + (size_t)row * CH + seg * 8);
        }
        cpa_commit();
        cpa_wait0();
    }
    __syncthreads();

    float d[2][8][4];
    #pragma unroll
    for (int mi = 0; mi < 2; mi++)
        #pragma unroll
        for (int nb = 0; nb < 8; nb++)
            #pragma unroll
            for (int r = 0; r < 4; r++) d[mi][nb][r] = 0.f;

    const char* whb = (const char*)g_wh;
    #pragma unroll 4
    for (int ks = 0; ks < 16; ks++) {
        const int kby = ks * 32 + (lane & 3) * 4;
        u32 a[2][4];
        #pragma unroll
        for (int mi = 0; mi < 2; mi++) {
            const char* pa = whb + (size_t)(rbase + mi * 16 + lr4) * 512 + kby;
            a[mi][0] = *(const u32*)pa;
            a[mi][1] = *(const u32*)(pa + 4096);
            a[mi][2] = *(const u32*)(pa + 16);
            a[mi][3] = *(const u32*)(pa + 4096 + 16);
        }
        #pragma unroll
        for (int nb = 0; nb < 8; nb++) {
            const char* pb = sm + (nb * 8 + lr4) * GX_PITCH + kby;
            u32 b0 = *(const u32*)pb;
            u32 b1 = *(const u32*)(pb + 16);
            mma16816h(d[0][nb], a[0][0], a[0][1], a[0][2], a[0][3], b0, b1);
            mma16816h(d[1][nb], a[1][0], a[1][1], a[1][2], a[1][3], b0, b1);
        }
    }

    // v epilogue (warps 2..9): bf16 store with bias
    if (!is_qk) {
        #pragma unroll
        for (int mi = 0; mi < 2; mi++) {
            int c0 = rbase - 64 + mi * 16 + lr4;
            int c1 = c0 + 8;
            float bv0 = bv[c0], bv1 = bv[c1];
            #pragma unroll
            for (int nb = 0; nb < 8; nb++) {
                int n = m0 + nb * 8 + lc2;
                u32 w0 = bf2(d[mi][nb][0] + bv0, d[mi][nb][1] + bv0);
                u32 w1 = bf2(d[mi][nb][2] + bv1, d[mi][nb][3] + bv1);
                *(u32*)((char*)g_v + ((size_t)(b * CH + c0) * NPOS + n) * 2) = w0;
                *(u32*)((char*)g_v + ((size_t)(b * CH + c1) * NPOS + n) * 2) = w1;
            }
        }
    }

    // q/k epilogue: bounce through smem, transpose, store fp16
    __syncthreads();
    float* bounce = (float*)sm;          // [64 n][68 r-pitch] f32 = 17408 B
    if (is_qk) {
        #pragma unroll
        for (int mi = 0; mi < 2; mi++) {
            int r = rbase + mi * 16 + lr4;
            #pragma unroll
            for (int nb = 0; nb < 8; nb++) {
                int n = nb * 8 + lc2;
                bounce[n * 68 + r]           = d[mi][nb][0];
                bounce[(n + 1) * 68 + r]     = d[mi][nb][1];
                bounce[n * 68 + r + 8]       = d[mi][nb][2];
                bounce[(n + 1) * 68 + r + 8] = d[mi][nb][3];
            }
        }
    }
    __syncthreads();

    for (int i = tid; i < 2048; i += 320) {
        int n = i >> 5, rp = i & 31;
        float2 f = *(const float2*)(bounce + n * 68 + rp * 2);
        bool isq = (rp < 16);
        int lr = isq ? 2 * rp : 2 * rp - 32;
        float b0 = isq ? bq[lr]     : bk[lr];
        float b1 = isq ? bq[lr + 1] : bk[lr + 1];
        u32 hw = hf2(f.x + b0, f.y + b1);
        size_t base = (((size_t)b * NPOS + m0 + n) * IDIM + lr) * 2;   // bytes
        if (isq) *(u32*)((char*)g_qh + base) = hw;
        else     *(u32*)((char*)g_kh + base) = hw;
    }
}

// ---------------------------------------------------------------------------
// Kernel 2: attention, fused pipeline (R9 structure), fp16 S / bf16 PV.
// 512 threads, M-tile 128, chunk 64 keys. P/V/K double-buffered, Q persistent.
// ---------------------------------------------------------------------------
#define LARR_OFF 0
#define AQ_OFF   1024                    // [128 m][80B] fp16              10240
#define AK_OFF   (AQ_OFF + 10240)        // 2 bufs x [64 n][80B] fp16      10240
#define AP_OFF   (AK_OFF + 10240)        // 2 bufs x [128 m][144B] bf16    36864
#define AV_OFF   (AP_OFF + 36864)        // 2 bufs x [256 c][144B] bf16    73728
#define ASM_TOT  (AV_OFF + 73728)        // 132096 B

// PV fused step: O[32m x 64c] += P[.,16k] * V[.,16k]^T  (bf16)
__device__ __forceinline__ void pv_step(const char* Pb, const char* Vb, int t,
        int mb2, int cb0, int lr4, int lc2, float (*o)[8][4])
{
    const int kby = (t * 16 + lc2) * 2;
    u32 a[2][4];
    #pragma unroll
    for (int mi = 0; mi < 2; mi++) {
        const char* pa = Pb + (mb2 + mi * 16 + lr4) * 144 + kby;
        a[mi][0] = *(const u32*)pa;
        a[mi][1] = *(const u32*)(pa + 8 * 144);
        a[mi][2] = *(const u32*)(pa + 16);
        a[mi][3] = *(const u32*)(pa + 8 * 144 + 16);
    }
    #pragma unroll
    for (int cj = 0; cj < 8; cj++) {
        const char* pb = Vb + (cb0 + cj * 8 + lr4) * 144 + kby;
        u32 b0 = *(const u32*)pb;
        u32 b1 = *(const u32*)(pb + 16);
        mma16816(o[0][cj], a[0][0], a[0][1], a[0][2], a[0][3], b0, b1);
        mma16816(o[1][cj], a[1][0], a[1][1], a[1][2], a[1][3], b0, b1);
    }
}

// S fused step: S[16q x 8n] via single-plane fp16 (2 MMAs) -> exp -> P (bf16)
__device__ __forceinline__ void s_step(const char* Kb, char* Pd, int t,
        int h, int mA, int lr4, int lc2, const u32 (*ah)[4],
        u64& lrA2, u64& lrB2)
{
    const int nbase = 32 * h + t * 8;
    float d[4] = {0.f, 0.f, 0.f, 0.f};
    #pragma unroll
    for (int ks = 0; ks < 2; ks++) {
        int kby = (ks * 16 + lc2) * 2;
        const char* pbh = Kb + (nbase + lr4) * 80 + kby;
        u32 b0 = *(const u32*)pbh;
        u32 b1 = *(const u32*)(pbh + 16);
        mma16816h(d, ah[ks][0], ah[ks][1], ah[ks][2], ah[ks][3], b0, b1);
    }
    float pA0, pA1, pB0, pB1;
    exp_pair(d[0], d[1], pA0, pA1);
    exp_pair(d[2], d[3], pB0, pB1);
    lrA2 = fadd2(lrA2, pack2(pA0, pA1));
    lrB2 = fadd2(lrB2, pack2(pB0, pB1));
    const int c0 = nbase + lc2;
    *(u32*)(Pd + mA * 144 + c0 * 2)       = bf2(pA0, pA1);
    *(u32*)(Pd + (mA + 8) * 144 + c0 * 2) = bf2(pB0, pB1);
}

__global__ __launch_bounds__(512, 1)
void attn_kernel(const float* __restrict__ x,
                 const float* __restrict__ gamma,
                 float* __restrict__ out)
{
    extern __shared__ char sm[];
    float* larr = (float*)(sm + LARR_OFF);
    const u32 smb = smem_u32(sm);

    const int b    = blockIdx.y;
    const int m0   = blockIdx.x * 128;
    const int tid  = threadIdx.x;
    const int w    = tid >> 5;
    const int lane = tid & 31;
    const int g    = w >> 1;        // S: q-group
    const int h    = w & 1;         // S: 32-key half
    const int lr4  = lane >> 2;
    const int lc2  = (lane & 3) * 2;
    const int mb2  = (w & 3) * 32;  // PV m-block
    const int cb0  = (w >> 2) * 64; // PV c-block

    const __half* qhb = g_qh + ((size_t)b * NPOS + m0) * IDIM;
    const __half* khb = g_kh + (size_t)b * NPOS * IDIM;
    const __nv_bfloat16* vb = g_v + (size_t)b * CH * NPOS;

    auto stage_K = [&](int buf, int n0) {
        if (tid < 256) {
            int j = tid & 3, row = tid >> 2;
            cpa16(smb + AK_OFF + buf * 5120 + row * 80 + j * 16,
                  khb + (size_t)(n0 + row) * IDIM + j * 8);
        }
    };
    auto stage_V = [&](int buf, int n0) {
        #pragma unroll
        for (int it = 0; it < 4; it++) {
            int idx = tid + it * 512;
            int c = idx >> 3, j = idx & 7;
            cpa16(smb + AV_OFF + buf * 36864 + c * 144 + j * 16,
                  vb + (size_t)c * NPOS + n0 + j * 8);
        }
    };

    // ---- Prologue ----
    {   // Q: 512 ops, exactly one per thread
        int j = tid & 3, row = tid >> 2;
        cpa16(smb + AQ_OFF + row * 80 + j * 16, qhb + (size_t)row * IDIM + j * 8);
    }
    stage_K(0, 0);
    cpa_commit();                              // G0: Q + K(0)
    stage_V(0, 0);
    stage_K(1, 64);
    cpa_commit();                              // G1: V(0) + K(1)
    cpa_wait1();                               // Q, K(0) landed
    __syncthreads();

    // Q a-frags (persistent registers, fp16)
    u32 ah[2][4];
    #pragma unroll
    for (int ks = 0; ks < 2; ks++) {
        int kby = (ks * 16 + lc2) * 2;
        const char* pah = sm + AQ_OFF + (g * 16 + lr4) * 80 + kby;
        ah[ks][0] = *(const u32*)(pah);
        ah[ks][1] = *(const u32*)(pah + 8 * 80);
        ah[ks][2] = *(const u32*)(pah + 16);
        ah[ks][3] = *(const u32*)(pah + 8 * 80 + 16);
    }

    float o[2][8][4];
    #pragma unroll
    for (int mi = 0; mi < 2; mi++)
        #pragma unroll
        for (int cj = 0; cj < 8; cj++)
            #pragma unroll
            for (int r = 0; r < 4; r++) o[mi][cj][r] = 0.f;
    u64 lrA2 = 0ull, lrB2 = 0ull;
    const int mA = g * 16 + lr4;

    // S(0) peeled
    #pragma unroll
    for (int t = 0; t < 4; t++)
        s_step(sm + AK_OFF, sm + AP_OFF, t, h, mA, lr4, lc2, ah, lrA2, lrB2);
    cpa_wait0();                               // V(0), K(1) landed
    __syncthreads();                           // P(0) visible

    // ---- Main loop: iter kk does PV(kk) + S(kk+1) ----
    #pragma unroll 1
    for (int kk = 0; kk < 63; kk++) {
        stage_V((kk + 1) & 1, (kk + 1) * 64);
        if (kk < 62) stage_K(kk & 1, (kk + 2) * 64);
        cpa_commit();

        const char* Pb = sm + AP_OFF + (kk & 1) * 18432;
        const char* Vb = sm + AV_OFF + (kk & 1) * 36864;
        const char* Kb = sm + AK_OFF + ((kk + 1) & 1) * 5120;
        char*       Pd = sm + AP_OFF + ((kk + 1) & 1) * 18432;

        #pragma unroll
        for (int t = 0; t < 4; t++) {
            pv_step(Pb, Vb, t, mb2, cb0, lr4, lc2, o);
            s_step(Kb, Pd, t, h, mA, lr4, lc2, ah, lrA2, lrB2);
        }
        cpa_wait0();
        __syncthreads();
    }

    // Final PV(63)
    #pragma unroll
    for (int t = 0; t < 4; t++)
        pv_step(sm + AP_OFF + 18432, sm + AV_OFF + 36864, t, mb2, cb0, lr4, lc2, o);

    // ---- l reduction ----
    {
        float2 fa = unpack2(lrA2);
        float2 fb = unpack2(lrB2);
        float lA = fa.x + fa.y;
        float lB = fb.x + fb.y;
        #pragma unroll
        for (int off = 1; off <= 2; off <<= 1) {
            lA += __shfl_xor_sync(0xffffffffu, lA, off);
            lB += __shfl_xor_sync(0xffffffffu, lB, off);
        }
        if ((lane & 3) == 0) {
            larr[h * 128 + g * 16 + lr4]     = lA;
            larr[h * 128 + g * 16 + lr4 + 8] = lB;
        }
    }
    __syncthreads();

    // ---- Epilogue ----
    const float gm = gamma[0];
    const size_t gbase = (size_t)b * CH * NPOS + m0;
    #pragma unroll
    for (int mi = 0; mi < 2; mi++) {
        const int mAe = mb2 + mi * 16 + lr4;
        const int mBe = mAe + 8;
        const float recA = gm / (larr[mAe] + larr[128 + mAe]);
        const float recB = gm / (larr[mBe] + larr[128 + mBe]);
        #pragma unroll
        for (int cj = 0; cj < 8; cj++) {
            const int c0 = cb0 + cj * 8 + lc2;
            size_t gi0 = gbase + (size_t)c0 * NPOS;
            out[gi0 + mAe]        = o[mi][cj][0] * recA + x[gi0 + mAe];
            out[gi0 + NPOS + mAe] = o[mi][cj][1] * recA + x[gi0 + NPOS + mAe];
            out[gi0 + mBe]        = o[mi][cj][2] * recB + x[gi0 + mBe];
            out[gi0 + NPOS + mBe] = o[mi][cj][3] * recB + x[gi0 + NPOS + mBe];
        }
    }
}

// ---------------------------------------------------------------------------
extern "C" void kernel_launch(void* const* d_in, const int* in_sizes, int n_in,
                              void* d_out, int out_size)
{
    const float* x     = (const float*)d_in[0];
    const float* Wq    = (const float*)d_in[1];
    const float* bq    = (const float*)d_in[2];
    const float* Wk    = (const float*)d_in[3];
    const float* bk    = (const float*)d_in[4];
    const float* Wv    = (const float*)d_in[5];
    const float* bv    = (const float*)d_in[6];
    const float* gamma = (const float*)d_in[7];
    float* out = (float*)d_out;

    cudaFuncSetAttribute(qkv_gemm,    cudaFuncAttributeMaxDynamicSharedMemorySize, GSM_TOT);
    cudaFuncSetAttribute(attn_kernel, cudaFuncAttributeMaxDynamicSharedMemorySize, ASM_TOT);

    xprep_kernel<<<dim3(64, 8), 256>>>(x);
    wprep_kernel<<<10, 256>>>(Wq, Wk, Wv);
    qkv_gemm<<<dim3(64, 8), 320, GSM_TOT>>>(bq, bk, bv);
    attn_kernel<<<dim3(32, 8), 512, ASM_TOT>>>(x, gamma, out);
}

// round 12
// speedup vs baseline: 1.9169x; 1.0723x over previous
#include <cuda_runtime.h>
#include <cuda_bf16.h>
#include <cuda_fp16.h>

#define BATCH 8
#define CH    256
#define NPOS  4096
#define IDIM  32

typedef unsigned long long u64;
typedef unsigned int u32;

__device__ __forceinline__ u64 pack2(float lo, float hi) {
    u64 r; asm("mov.b64 %0, {%1, %2};" : "=l"(r) : "f"(lo), "f"(hi)); return r;
}
__device__ __forceinline__ u64 ffma2(u64 a, u64 b, u64 c) {
    u64 d; asm("fma.rn.f32x2 %0, %1, %2, %3;" : "=l"(d) : "l"(a), "l"(b), "l"(c)); return d;
}
__device__ __forceinline__ u64 fmul2(u64 a, u64 b) {
    u64 d; asm("mul.rn.f32x2 %0, %1, %2;" : "=l"(d) : "l"(a), "l"(b)); return d;
}
__device__ __forceinline__ u64 fadd2(u64 a, u64 b) {
    u64 d; asm("add.rn.f32x2 %0, %1, %2;" : "=l"(d) : "l"(a), "l"(b)); return d;
}
__device__ __forceinline__ float2 unpack2(u64 a) {
    float2 f; asm("mov.b64 {%0, %1}, %2;" : "=f"(f.x), "=f"(f.y) : "l"(a)); return f;
}
__device__ __forceinline__ u32 bf2(float lo, float hi) {   // {lo16, hi16} packed bf16x2
    u32 r; asm("cvt.rn.bf16x2.f32 %0, %1, %2;" : "=r"(r) : "f"(hi), "f"(lo)); return r;
}
__device__ __forceinline__ u32 hf2(float lo, float hi) {   // {lo16, hi16} packed f16x2
    u32 r; asm("cvt.rn.f16x2.f32 %0, %1, %2;" : "=r"(r) : "f"(hi), "f"(lo)); return r;
}
__device__ __forceinline__ u32 smem_u32(const void* p) {
    u32 a; asm("{ .reg .u64 t; cvta.to.shared.u64 t, %1; cvt.u32.u64 %0, t; }" : "=r"(a) : "l"(p));
    return a;
}
// bf16 MMA (PV path)
__device__ __forceinline__ void mma16816(float* d, u32 a0, u32 a1, u32 a2, u32 a3,
                                         u32 b0, u32 b1) {
    asm volatile("mma.sync.aligned.m16n8k16.row.col.f32.bf16.bf16.f32 "
                 "{%0,%1,%2,%3}, {%4,%5,%6,%7}, {%8,%9}, {%0,%1,%2,%3};"
                 : "+f"(d[0]), "+f"(d[1]), "+f"(d[2]), "+f"(d[3])
                 : "r"(a0), "r"(a1), "r"(a2), "r"(a3), "r"(b0), "r"(b1));
}
// fp16 MMA (S path + qkv GEMM)
__device__ __forceinline__ void mma16816h(float* d, u32 a0, u32 a1, u32 a2, u32 a3,
                                          u32 b0, u32 b1) {
    asm volatile("mma.sync.aligned.m16n8k16.row.col.f32.f16.f16.f32 "
                 "{%0,%1,%2,%3}, {%4,%5,%6,%7}, {%8,%9}, {%0,%1,%2,%3};"
                 : "+f"(d[0]), "+f"(d[1]), "+f"(d[2]), "+f"(d[3])
                 : "r"(a0), "r"(a1), "r"(a2), "r"(a3), "r"(b0), "r"(b1));
}
__device__ __forceinline__ void cpa16(u32 dst, const void* src) {
    asm volatile("cp.async.cg.shared.global [%0], [%1], 16;" :: "r"(dst), "l"(src));
}
__device__ __forceinline__ void cpa_commit() { asm volatile("cp.async.commit_group;" ::: "memory"); }
__device__ __forceinline__ void cpa_wait0()  { asm volatile("cp.async.wait_group 0;" ::: "memory"); }
__device__ __forceinline__ void cpa_wait1()  { asm volatile("cp.async.wait_group 1;" ::: "memory"); }

// Fast exp on the FMA pipe (no MUFU)
__device__ __forceinline__ void exp_pair(float s0, float s1, float& p0, float& p1) {
    const float MAGIC = 12582912.f;   // 1.5 * 2^23
    u64 t2  = fmul2(pack2(s0, s1), pack2(1.4426950408889634f, 1.4426950408889634f));
    u64 r2  = fadd2(t2, pack2(MAGIC, MAGIC));
    u64 rm2 = fadd2(r2, pack2(-MAGIC, -MAGIC));
    u64 f2  = ffma2(rm2, pack2(-1.f, -1.f), t2);
    u64 q2  = ffma2(f2, pack2(1.3333558146e-3f, 1.3333558146e-3f),
                        pack2(9.6181291076e-3f, 9.6181291076e-3f));
    q2 = ffma2(f2, q2, pack2(5.5504108664e-2f, 5.5504108664e-2f));
    q2 = ffma2(f2, q2, pack2(2.4022650696e-1f, 2.4022650696e-1f));
    q2 = ffma2(f2, q2, pack2(6.9314718056e-1f, 6.9314718056e-1f));
    q2 = ffma2(f2, q2, pack2(1.f, 1.f));
    float2 rr = unpack2(r2);
    float2 qq = unpack2(q2);
    int e0 = (__float_as_int(rr.x) - 0x4B400000) << 23;
    int e1 = (__float_as_int(rr.y) - 0x4B400000) << 23;
    p0 = __int_as_float(__float_as_int(qq.x) + e0);
    p1 = __int_as_float(__float_as_int(qq.y) + e1);
}

// Scratch
__device__ __half g_wh[320 * CH];                     // W fp16 [320 r][256 c]
__device__ __half g_qh[BATCH * NPOS * IDIM];          // q fp16 [b][m][32 i]
__device__ __half g_kh[BATCH * NPOS * IDIM];          // k fp16 [b][n][32 i]
__device__ __nv_bfloat16 g_v[BATCH * CH * NPOS];      // v bf16 [b][c][n]

// ---------------------------------------------------------------------------
// Kernel 0: W (320 x 256) -> fp16
// ---------------------------------------------------------------------------
__global__ __launch_bounds__(256, 4)
void wprep_kernel(const float* __restrict__ Wq, const float* __restrict__ Wk,
                  const float* __restrict__ Wv)
{
    const int gidx = blockIdx.x * 256 + threadIdx.x;
    #pragma unroll
    for (int i = 0; i < 8; i++) {
        int idx4 = gidx + i * 2560;
        int el = idx4 * 4;
        int r = el >> 8, c = el & 255;
        const float* src;
        if (r < 32)       src = Wq + r * CH + c;
        else if (r < 64)  src = Wk + (r - 32) * CH + c;
        else              src = Wv + (r - 64) * CH + c;
        float4 wv = *(const float4*)src;
        *(uint2*)((char*)g_wh + (size_t)el * 2) =
            make_uint2(hf2(wv.x, wv.y), hf2(wv.z, wv.w));
    }
}

// ---------------------------------------------------------------------------
// Kernel 1: QKV GEMM, fp16 HMMA, x converted in-kernel (xprep fused).
// grid (64,8), 320 threads. Warp w: rows w*32..+31 (w<2: q/k; else v).
// ---------------------------------------------------------------------------
#define GX_PITCH 528
#define GSM_TOT  33792

__global__ __launch_bounds__(320, 2)
void qkv_gemm(const float* __restrict__ x,
              const float* __restrict__ bq, const float* __restrict__ bk,
              const float* __restrict__ bv)
{
    extern __shared__ char sm[];

    const int b    = blockIdx.y;
    const int m0   = blockIdx.x * 64;
    const int tid  = threadIdx.x;
    const int w    = tid >> 5;
    const int lane = tid & 31;
    const int lr4  = lane >> 2;
    const int lc2  = (lane & 3) * 2;
    const int rbase = w * 32;
    const bool is_qk = (w < 2);

    // Stage X tile [64 n][256 c] fp16, converting from fp32 [c][n] directly
    {
        const float* xb = x + (size_t)b * CH * NPOS;
        for (int i = tid; i < 2048; i += 320) {
            int cp = i & 127, nq = i >> 7;          // c-pair, n-quad
            const float* p0 = xb + (size_t)(2 * cp) * NPOS + m0 + nq * 4;
            float4 a  = *(const float4*)p0;
            float4 c4 = *(const float4*)(p0 + NPOS);
            float av[4] = {a.x, a.y, a.z, a.w};
            float cv[4] = {c4.x, c4.y, c4.z, c4.w};
            #pragma unroll
            for (int e = 0; e < 4; e++)
                *(u32*)(sm + (nq * 4 + e) * GX_PITCH + cp * 4) = hf2(av[e], cv[e]);
        }
    }
    __syncthreads();

    float d[2][8][4];
    #pragma unroll
    for (int mi = 0; mi < 2; mi++)
        #pragma unroll
        for (int nb = 0; nb < 8; nb++)
            #pragma unroll
            for (int r = 0; r < 4; r++) d[mi][nb][r] = 0.f;

    const char* whb = (const char*)g_wh;
    #pragma unroll 4
    for (int ks = 0; ks < 16; ks++) {
        const int kby = ks * 32 + (lane & 3) * 4;
        u32 a[2][4];
        #pragma unroll
        for (int mi = 0; mi < 2; mi++) {
            const char* pa = whb + (size_t)(rbase + mi * 16 + lr4) * 512 + kby;
            a[mi][0] = *(const u32*)pa;
            a[mi][1] = *(const u32*)(pa + 4096);
            a[mi][2] = *(const u32*)(pa + 16);
            a[mi][3] = *(const u32*)(pa + 4096 + 16);
        }
        #pragma unroll
        for (int nb = 0; nb < 8; nb++) {
            const char* pb = sm + (nb * 8 + lr4) * GX_PITCH + kby;
            u32 b0 = *(const u32*)pb;
            u32 b1 = *(const u32*)(pb + 16);
            mma16816h(d[0][nb], a[0][0], a[0][1], a[0][2], a[0][3], b0, b1);
            mma16816h(d[1][nb], a[1][0], a[1][1], a[1][2], a[1][3], b0, b1);
        }
    }

    // v epilogue (warps 2..9): bf16 store with bias
    if (!is_qk) {
        #pragma unroll
        for (int mi = 0; mi < 2; mi++) {
            int c0 = rbase - 64 + mi * 16 + lr4;
            int c1 = c0 + 8;
            float bv0 = bv[c0], bv1 = bv[c1];
            #pragma unroll
            for (int nb = 0; nb < 8; nb++) {
                int n = m0 + nb * 8 + lc2;
                u32 w0 = bf2(d[mi][nb][0] + bv0, d[mi][nb][1] + bv0);
                u32 w1 = bf2(d[mi][nb][2] + bv1, d[mi][nb][3] + bv1);
                *(u32*)((char*)g_v + ((size_t)(b * CH + c0) * NPOS + n) * 2) = w0;
                *(u32*)((char*)g_v + ((size_t)(b * CH + c1) * NPOS + n) * 2) = w1;
            }
        }
    }

    // q/k epilogue: bounce through smem, transpose, store fp16
    __syncthreads();
    float* bounce = (float*)sm;          // [64 n][68 r-pitch] f32 = 17408 B
    if (is_qk) {
        #pragma unroll
        for (int mi = 0; mi < 2; mi++) {
            int r = rbase + mi * 16 + lr4;
            #pragma unroll
            for (int nb = 0; nb < 8; nb++) {
                int n = nb * 8 + lc2;
                bounce[n * 68 + r]           = d[mi][nb][0];
                bounce[(n + 1) * 68 + r]     = d[mi][nb][1];
                bounce[n * 68 + r + 8]       = d[mi][nb][2];
                bounce[(n + 1) * 68 + r + 8] = d[mi][nb][3];
            }
        }
    }
    __syncthreads();

    for (int i = tid; i < 2048; i += 320) {
        int n = i >> 5, rp = i & 31;
        float2 f = *(const float2*)(bounce + n * 68 + rp * 2);
        bool isq = (rp < 16);
        int lr = isq ? 2 * rp : 2 * rp - 32;
        float b0 = isq ? bq[lr]     : bk[lr];
        float b1 = isq ? bq[lr + 1] : bk[lr + 1];
        u32 hw = hf2(f.x + b0, f.y + b1);
        size_t base = (((size_t)b * NPOS + m0 + n) * IDIM + lr) * 2;   // bytes
        if (isq) *(u32*)((char*)g_qh + base) = hw;
        else     *(u32*)((char*)g_kh + base) = hw;
    }
}

// ---------------------------------------------------------------------------
// Kernel 2: attention, fused pipeline, exp staggered one t-step behind.
// 512 threads, M-tile 128, chunk 64 keys. P/V/K double-buffered, Q persistent.
// ---------------------------------------------------------------------------
#define LARR_OFF 0
#define AQ_OFF   1024                    // [128 m][80B] fp16              10240
#define AK_OFF   (AQ_OFF + 10240)        // 2 bufs x [64 n][80B] fp16      10240
#define AP_OFF   (AK_OFF + 10240)        // 2 bufs x [128 m][144B] bf16    36864
#define AV_OFF   (AP_OFF + 36864)        // 2 bufs x [256 c][144B] bf16    73728
#define ASM_TOT  (AV_OFF + 73728)        // 132096 B

// PV fused step: O[32m x 64c] += P[.,16k] * V[.,16k]^T  (bf16)
__device__ __forceinline__ void pv_step(const char* Pb, const char* Vb, int t,
        int mb2, int cb0, int lr4, int lc2, float (*o)[8][4])
{
    const int kby = (t * 16 + lc2) * 2;
    u32 a[2][4];
    #pragma unroll
    for (int mi = 0; mi < 2; mi++) {
        const char* pa = Pb + (mb2 + mi * 16 + lr4) * 144 + kby;
        a[mi][0] = *(const u32*)pa;
        a[mi][1] = *(const u32*)(pa + 8 * 144);
        a[mi][2] = *(const u32*)(pa + 16);
        a[mi][3] = *(const u32*)(pa + 8 * 144 + 16);
    }
    #pragma unroll
    for (int cj = 0; cj < 8; cj++) {
        const char* pb = Vb + (cb0 + cj * 8 + lr4) * 144 + kby;
        u32 b0 = *(const u32*)pb;
        u32 b1 = *(const u32*)(pb + 16);
        mma16816(o[0][cj], a[0][0], a[0][1], a[0][2], a[0][3], b0, b1);
        mma16816(o[1][cj], a[1][0], a[1][1], a[1][2], a[1][3], b0, b1);
    }
}

// S MMA only: S[16q x 8n] via fp16 (2 MMAs) -> regs
__device__ __forceinline__ void s_mma(const char* Kb, int t,
        int h, int lr4, int lc2, const u32 (*ah)[4], float* d)
{
    const int nbase = 32 * h + t * 8;
    d[0] = d[1] = d[2] = d[3] = 0.f;
    #pragma unroll
    for (int ks = 0; ks < 2; ks++) {
        int kby = (ks * 16 + lc2) * 2;
        const char* pbh = Kb + (nbase + lr4) * 80 + kby;
        u32 b0 = *(const u32*)pbh;
        u32 b1 = *(const u32*)(pbh + 16);
        mma16816h(d, ah[ks][0], ah[ks][1], ah[ks][2], ah[ks][3], b0, b1);
    }
}

// S finish: exp + l accum + P store (issued one t-step later for latency hiding)
__device__ __forceinline__ void s_finish(char* Pd, int t,
        int h, int mA, int lc2, const float* d, u64& lrA2, u64& lrB2)
{
    float pA0, pA1, pB0, pB1;
    exp_pair(d[0], d[1], pA0, pA1);
    exp_pair(d[2], d[3], pB0, pB1);
    lrA2 = fadd2(lrA2, pack2(pA0, pA1));
    lrB2 = fadd2(lrB2, pack2(pB0, pB1));
    const int c0 = 32 * h + t * 8 + lc2;
    *(u32*)(Pd + mA * 144 + c0 * 2)       = bf2(pA0, pA1);
    *(u32*)(Pd + (mA + 8) * 144 + c0 * 2) = bf2(pB0, pB1);
}

__global__ __launch_bounds__(512, 1)
void attn_kernel(const float* __restrict__ x,
                 const float* __restrict__ gamma,
                 float* __restrict__ out)
{
    extern __shared__ char sm[];
    float* larr = (float*)(sm + LARR_OFF);
    const u32 smb = smem_u32(sm);

    const int b    = blockIdx.y;
    const int m0   = blockIdx.x * 128;
    const int tid  = threadIdx.x;
    const int w    = tid >> 5;
    const int lane = tid & 31;
    const int g    = w >> 1;        // S: q-group
    const int h    = w & 1;         // S: 32-key half
    const int lr4  = lane >> 2;
    const int lc2  = (lane & 3) * 2;
    const int mb2  = (w & 3) * 32;  // PV m-block
    const int cb0  = (w >> 2) * 64; // PV c-block

    const __half* qhb = g_qh + ((size_t)b * NPOS + m0) * IDIM;
    const __half* khb = g_kh + (size_t)b * NPOS * IDIM;
    const __nv_bfloat16* vb = g_v + (size_t)b * CH * NPOS;

    auto stage_K = [&](int buf, int n0) {
        if (tid < 256) {
            int j = tid & 3, row = tid >> 2;
            cpa16(smb + AK_OFF + buf * 5120 + row * 80 + j * 16,
                  khb + (size_t)(n0 + row) * IDIM + j * 8);
        }
    };
    auto stage_V = [&](int buf, int n0) {
        #pragma unroll
        for (int it = 0; it < 4; it++) {
            int idx = tid + it * 512;
            int c = idx >> 3, j = idx & 7;
            cpa16(smb + AV_OFF + buf * 36864 + c * 144 + j * 16,
                  vb + (size_t)c * NPOS + n0 + j * 8);
        }
    };

    // ---- Prologue ----
    {   // Q: 512 ops, one per thread
        int j = tid & 3, row = tid >> 2;
        cpa16(smb + AQ_OFF + row * 80 + j * 16, qhb + (size_t)row * IDIM + j * 8);
    }
    stage_K(0, 0);
    cpa_commit();                              // G0: Q + K(0)
    stage_V(0, 0);
    stage_K(1, 64);
    cpa_commit();                              // G1: V(0) + K(1)
    cpa_wait1();                               // Q, K(0) landed
    __syncthreads();

    // Q a-frags (persistent registers, fp16)
    u32 ah[2][4];
    #pragma unroll
    for (int ks = 0; ks < 2; ks++) {
        int kby = (ks * 16 + lc2) * 2;
        const char* pah = sm + AQ_OFF + (g * 16 + lr4) * 80 + kby;
        ah[ks][0] = *(const u32*)(pah);
        ah[ks][1] = *(const u32*)(pah + 8 * 80);
        ah[ks][2] = *(const u32*)(pah + 16);
        ah[ks][3] = *(const u32*)(pah + 8 * 80 + 16);
    }

    float o[2][8][4];
    #pragma unroll
    for (int mi = 0; mi < 2; mi++)
        #pragma unroll
        for (int cj = 0; cj < 8; cj++)
            #pragma unroll
            for (int r = 0; r < 4; r++) o[mi][cj][r] = 0.f;
    u64 lrA2 = 0ull, lrB2 = 0ull;
    const int mA = g * 16 + lr4;

    float sd[2][4];

    // S(0) peeled, staggered within itself
    #pragma unroll
    for (int t = 0; t < 4; t++) {
        s_mma(sm + AK_OFF, t, h, lr4, lc2, ah, sd[t & 1]);
        if (t > 0) s_finish(sm + AP_OFF, t - 1, h, mA, lc2, sd[(t - 1) & 1], lrA2, lrB2);
    }
    s_finish(sm + AP_OFF, 3, h, mA, lc2, sd[1], lrA2, lrB2);
    cpa_wait0();                               // V(0), K(1) landed
    __syncthreads();                           // P(0) visible

    // ---- Main loop: iter kk does PV(kk) + S(kk+1), exp staggered ----
    #pragma unroll 1
    for (int kk = 0; kk < 63; kk++) {
        stage_V((kk + 1) & 1, (kk + 1) * 64);
        if (kk < 62) stage_K(kk & 1, (kk + 2) * 64);
        cpa_commit();

        const char* Pb = sm + AP_OFF + (kk & 1) * 18432;
        const char* Vb = sm + AV_OFF + (kk & 1) * 36864;
        const char* Kb = sm + AK_OFF + ((kk + 1) & 1) * 5120;
        char*       Pd = sm + AP_OFF + ((kk + 1) & 1) * 18432;

        #pragma unroll
        for (int t = 0; t < 4; t++) {
            pv_step(Pb, Vb, t, mb2, cb0, lr4, lc2, o);
            s_mma(Kb, t, h, lr4, lc2, ah, sd[t & 1]);
            if (t > 0) s_finish(Pd, t - 1, h, mA, lc2, sd[(t - 1) & 1], lrA2, lrB2);
        }
        s_finish(Pd, 3, h, mA, lc2, sd[1], lrA2, lrB2);
        cpa_wait0();
        __syncthreads();
    }

    // Final PV(63)
    #pragma unroll
    for (int t = 0; t < 4; t++)
        pv_step(sm + AP_OFF + 18432, sm + AV_OFF + 36864, t, mb2, cb0, lr4, lc2, o);

    // ---- l reduction ----
    {
        float2 fa = unpack2(lrA2);
        float2 fb = unpack2(lrB2);
        float lA = fa.x + fa.y;
        float lB = fb.x + fb.y;
        #pragma unroll
        for (int off = 1; off <= 2; off <<= 1) {
            lA += __shfl_xor_sync(0xffffffffu, lA, off);
            lB += __shfl_xor_sync(0xffffffffu, lB, off);
        }
        if ((lane & 3) == 0) {
            larr[h * 128 + g * 16 + lr4]     = lA;
            larr[h * 128 + g * 16 + lr4 + 8] = lB;
        }
    }
    __syncthreads();

    // ---- Epilogue ----
    const float gm = gamma[0];
    const size_t gbase = (size_t)b * CH * NPOS + m0;
    #pragma unroll
    for (int mi = 0; mi < 2; mi++) {
        const int mAe = mb2 + mi * 16 + lr4;
        const int mBe = mAe + 8;
        const float recA = gm / (larr[mAe] + larr[128 + mAe]);
        const float recB = gm / (larr[mBe] + larr[128 + mBe]);
        #pragma unroll
        for (int cj = 0; cj < 8; cj++) {
            const int c0 = cb0 + cj * 8 + lc2;
            size_t gi0 = gbase + (size_t)c0 * NPOS;
            out[gi0 + mAe]        = o[mi][cj][0] * recA + x[gi0 + mAe];
            out[gi0 + NPOS + mAe] = o[mi][cj][1] * recA + x[gi0 + NPOS + mAe];
            out[gi0 + mBe]        = o[mi][cj][2] * recB + x[gi0 + mBe];
            out[gi0 + NPOS + mBe] = o[mi][cj][3] * recB + x[gi0 + NPOS + mBe];
        }
    }
}

// ---------------------------------------------------------------------------
extern "C" void kernel_launch(void* const* d_in, const int* in_sizes, int n_in,
                              void* d_out, int out_size)
{
    const float* x     = (const float*)d_in[0];
    const float* Wq    = (const float*)d_in[1];
    const float* bq    = (const float*)d_in[2];
    const float* Wk    = (const float*)d_in[3];
    const float* bk    = (const float*)d_in[4];
    const float* Wv    = (const float*)d_in[5];
    const float* bv    = (const float*)d_in[6];
    const float* gamma = (const float*)d_in[7];
    float* out = (float*)d_out;

    cudaFuncSetAttribute(qkv_gemm,    cudaFuncAttributeMaxDynamicSharedMemorySize, GSM_TOT);
    cudaFuncSetAttribute(attn_kernel, cudaFuncAttributeMaxDynamicSharedMemorySize, ASM_TOT);

    wprep_kernel<<<10, 256>>>(Wq, Wk, Wv);
    qkv_gemm<<<dim3(64, 8), 320, GSM_TOT>>>(x, bq, bk, bv);
    attn_kernel<<<dim3(32, 8), 512, ASM_TOT>>>(x, gamma, out);
}